// round 2
// baseline (speedup 1.0000x reference)
#include <cuda_runtime.h>
#include <math.h>

#define T_FRAMES 128
#define V_VERTS  5023
#define K_NBR    16

__device__ __forceinline__ void jacobi_rotate(double S[3][3], double Vm[3][3], int p, int q) {
    double Spq = S[p][q];
    if (fabs(Spq) < 1e-300) return;
    double tau = (S[q][q] - S[p][p]) / (2.0 * Spq);
    double t;
    if (tau >= 0.0) t = 1.0 / (tau + sqrt(1.0 + tau * tau));
    else            t = -1.0 / (-tau + sqrt(1.0 + tau * tau));
    double c = 1.0 / sqrt(1.0 + t * t);
    double s = t * c;

    // Update S = J^T S J (symmetric)
    double Spp = S[p][p], Sqq = S[q][q];
    S[p][p] = Spp - t * Spq;
    S[q][q] = Sqq + t * Spq;
    S[p][q] = 0.0;
    S[q][p] = 0.0;
    int r = 3 - p - q; // the remaining index
    double Srp = S[r][p], Srq = S[r][q];
    S[r][p] = c * Srp - s * Srq;  S[p][r] = S[r][p];
    S[r][q] = s * Srp + c * Srq;  S[q][r] = S[r][q];

    // Update V = V J (rotate columns p,q)
    #pragma unroll
    for (int i = 0; i < 3; i++) {
        double vip = Vm[i][p], viq = Vm[i][q];
        Vm[i][p] = c * vip - s * viq;
        Vm[i][q] = s * vip + c * viq;
    }
}

__global__ void __launch_bounds__(256)
se3_extract_kernel(const float* __restrict__ canon,
                   const float* __restrict__ deform,
                   const int* __restrict__ neighbors,
                   const int* __restrict__ nmask,
                   float* __restrict__ out)
{
    int v = blockIdx.x * blockDim.x + threadIdx.x;
    int t = blockIdx.y;
    if (v >= V_VERTS) return;

    const float* ct = canon  + (size_t)t * V_VERTS * 3;
    const float* dt = deform + (size_t)t * V_VERTS * 3;

    float c0x = ct[v * 3 + 0], c0y = ct[v * 3 + 1], c0z = ct[v * 3 + 2];
    float d0x = dt[v * 3 + 0], d0y = dt[v * 3 + 1], d0z = dt[v * 3 + 2];

    // covariance accumulation: cov[i][j] = sum_k p_i * q_j
    float a00 = 0.f, a01 = 0.f, a02 = 0.f;
    float a10 = 0.f, a11 = 0.f, a12 = 0.f;
    float a20 = 0.f, a21 = 0.f, a22 = 0.f;

    #pragma unroll
    for (int k = 0; k < K_NBR; k++) {
        int n = __ldg(&neighbors[v * K_NBR + k]);
        float m = (__ldg(&nmask[v * K_NBR + k]) != 0) ? 1.0f : 0.0f;
        float px = __ldg(&ct[n * 3 + 0]) * m - c0x;
        float py = __ldg(&ct[n * 3 + 1]) * m - c0y;
        float pz = __ldg(&ct[n * 3 + 2]) * m - c0z;
        float qx = __ldg(&dt[n * 3 + 0]) * m - d0x;
        float qy = __ldg(&dt[n * 3 + 1]) * m - d0y;
        float qz = __ldg(&dt[n * 3 + 2]) * m - d0z;
        a00 += px * qx; a01 += px * qy; a02 += px * qz;
        a10 += py * qx; a11 += py * qy; a12 += py * qz;
        a20 += pz * qx; a21 += pz * qy; a22 += pz * qz;
    }

    double A[3][3] = {{a00, a01, a02}, {a10, a11, a12}, {a20, a21, a22}};

    // S = A^T A (symmetric)
    double S[3][3];
    #pragma unroll
    for (int i = 0; i < 3; i++)
        #pragma unroll
        for (int j = 0; j < 3; j++) {
            double acc = 0.0;
            #pragma unroll
            for (int k = 0; k < 3; k++) acc += A[k][i] * A[k][j];
            S[i][j] = acc;
        }

    double Vm[3][3] = {{1, 0, 0}, {0, 1, 0}, {0, 0, 1}};
    #pragma unroll
    for (int sweep = 0; sweep < 8; sweep++) {
        jacobi_rotate(S, Vm, 0, 1);
        jacobi_rotate(S, Vm, 0, 2);
        jacobi_rotate(S, Vm, 1, 2);
    }

    // eigenvalues on diagonal; sort descending with vectors (columns of Vm)
    double w[3] = {S[0][0], S[1][1], S[2][2]};
    int idx[3] = {0, 1, 2};
    #pragma unroll
    for (int i = 0; i < 2; i++)
        #pragma unroll
        for (int j = 0; j < 2 - i; j++)
            if (w[idx[j]] < w[idx[j + 1]]) { int tmp = idx[j]; idx[j] = idx[j + 1]; idx[j + 1] = tmp; }

    double V0[3], V1[3], V2[3];
    #pragma unroll
    for (int i = 0; i < 3; i++) {
        V0[i] = Vm[i][idx[0]];
        V1[i] = Vm[i][idx[1]];
        V2[i] = Vm[i][idx[2]];
    }

    // U columns: u_i = A v_i / sigma_i
    double U0[3], U1[3], U2[3];
    #pragma unroll
    for (int i = 0; i < 3; i++) {
        U0[i] = A[i][0] * V0[0] + A[i][1] * V0[1] + A[i][2] * V0[2];
        U1[i] = A[i][0] * V1[0] + A[i][1] * V1[1] + A[i][2] * V1[2];
        U2[i] = A[i][0] * V2[0] + A[i][1] * V2[1] + A[i][2] * V2[2];
    }
    double s0 = sqrt(U0[0]*U0[0] + U0[1]*U0[1] + U0[2]*U0[2]);
    double s1 = sqrt(U1[0]*U1[0] + U1[1]*U1[1] + U1[2]*U1[2]);
    double s2 = sqrt(U2[0]*U2[0] + U2[1]*U2[1] + U2[2]*U2[2]);

    double R[3][3];
    if (s0 < 1e-30) {
        // degenerate: cov ~ 0 -> identity rotation (matches SVD(0) convention)
        R[0][0] = 1; R[0][1] = 0; R[0][2] = 0;
        R[1][0] = 0; R[1][1] = 1; R[1][2] = 0;
        R[2][0] = 0; R[2][1] = 0; R[2][2] = 1;
    } else {
        double inv0 = 1.0 / s0;
        #pragma unroll
        for (int i = 0; i < 3; i++) U0[i] *= inv0;
        if (s1 > 1e-12 * s0) {
            double inv1 = 1.0 / s1;
            #pragma unroll
            for (int i = 0; i < 3; i++) U1[i] *= inv1;
        } else {
            // pick any unit vector orthogonal to U0
            double ax = fabs(U0[0]), ay = fabs(U0[1]), az = fabs(U0[2]);
            double e[3] = {0, 0, 0};
            if (ax <= ay && ax <= az) e[0] = 1; else if (ay <= az) e[1] = 1; else e[2] = 1;
            double d = e[0]*U0[0] + e[1]*U0[1] + e[2]*U0[2];
            double tx = e[0] - d*U0[0], ty = e[1] - d*U0[1], tz = e[2] - d*U0[2];
            double nrm = sqrt(tx*tx + ty*ty + tz*tz);
            U1[0] = tx / nrm; U1[1] = ty / nrm; U1[2] = tz / nrm;
        }
        if (s2 > 1e-12 * s0) {
            double inv2 = 1.0 / s2;
            #pragma unroll
            for (int i = 0; i < 3; i++) U2[i] *= inv2;
        } else {
            // U2 = U0 x U1 (sign free when sigma2 == 0; d3 compensates via det)
            U2[0] = U0[1]*U1[2] - U0[2]*U1[1];
            U2[1] = U0[2]*U1[0] - U0[0]*U1[2];
            U2[2] = U0[0]*U1[1] - U0[1]*U1[0];
        }

        // det(U) and det(V) via triple products
        double detU = U0[0]*(U1[1]*U2[2] - U1[2]*U2[1])
                    - U0[1]*(U1[0]*U2[2] - U1[2]*U2[0])
                    + U0[2]*(U1[0]*U2[1] - U1[1]*U2[0]);
        double detV = V0[0]*(V1[1]*V2[2] - V1[2]*V2[1])
                    - V0[1]*(V1[0]*V2[2] - V1[2]*V2[0])
                    + V0[2]*(V1[0]*V2[1] - V1[1]*V2[0]);
        double detUV = detU * detV;
        double d3 = (fabs(detUV - 1.0) > 1e-6) ? detUV : 1.0;

        // R = V * diag(1,1,d3) * U^T  = v0 u0^T + v1 u1^T + d3 * v2 u2^T
        #pragma unroll
        for (int a = 0; a < 3; a++)
            #pragma unroll
            for (int b = 0; b < 3; b++)
                R[a][b] = V0[a]*U0[b] + V1[a]*U1[b] + d3 * V2[a]*U2[b];
    }

    // ---- matrix -> quaternion (pytorch3d-style 4-candidate selection) ----
    double m00 = R[0][0], m01 = R[0][1], m02 = R[0][2];
    double m10 = R[1][0], m11 = R[1][1], m12 = R[1][2];
    double m20 = R[2][0], m21 = R[2][1], m22 = R[2][2];

    double qa0 = 1.0 + m00 + m11 + m22;
    double qa1 = 1.0 + m00 - m11 - m22;
    double qa2 = 1.0 - m00 + m11 - m22;
    double qa3 = 1.0 - m00 - m11 + m22;
    qa0 = sqrt(qa0 > 0.0 ? qa0 : 0.0);
    qa1 = sqrt(qa1 > 0.0 ? qa1 : 0.0);
    qa2 = sqrt(qa2 > 0.0 ? qa2 : 0.0);
    qa3 = sqrt(qa3 > 0.0 ? qa3 : 0.0);

    // argmax (first max on ties, like jnp.argmax)
    double qabs[4] = {qa0, qa1, qa2, qa3};
    int imax = 0;
    #pragma unroll
    for (int i = 1; i < 4; i++) if (qabs[i] > qabs[imax]) imax = i;

    double cand[4];
    if (imax == 0) {
        cand[0] = qa0 * qa0; cand[1] = m21 - m12; cand[2] = m02 - m20; cand[3] = m10 - m01;
    } else if (imax == 1) {
        cand[0] = m21 - m12; cand[1] = qa1 * qa1; cand[2] = m01 + m10; cand[3] = m02 + m20;
    } else if (imax == 2) {
        cand[0] = m02 - m20; cand[1] = m10 + m01; cand[2] = qa2 * qa2; cand[3] = m12 + m21;
    } else {
        cand[0] = m10 - m01; cand[1] = m20 + m02; cand[2] = m21 + m12; cand[3] = qa3 * qa3;
    }
    double denom = 2.0 * (qabs[imax] > 0.1 ? qabs[imax] : 0.1);
    double invd = 1.0 / denom;

    size_t tv = (size_t)t * V_VERTS + v;
    float* rot_out = out;                                   // [T*V, 4]
    float* trn_out = out + (size_t)T_FRAMES * V_VERTS * 4;  // [T*V, 3]

    rot_out[tv * 4 + 0] = (float)(cand[0] * invd);
    rot_out[tv * 4 + 1] = (float)(cand[1] * invd);
    rot_out[tv * 4 + 2] = (float)(cand[2] * invd);
    rot_out[tv * 4 + 3] = (float)(cand[3] * invd);

    trn_out[tv * 3 + 0] = d0x - c0x;
    trn_out[tv * 3 + 1] = d0y - c0y;
    trn_out[tv * 3 + 2] = d0z - c0z;
}

extern "C" void kernel_launch(void* const* d_in, const int* in_sizes, int n_in,
                              void* d_out, int out_size) {
    const float* canon  = (const float*)d_in[0];
    const float* deform = (const float*)d_in[1];
    const int*   neigh  = (const int*)d_in[2];
    const int*   nmask  = (const int*)d_in[3];
    float* out = (float*)d_out;

    dim3 block(256, 1, 1);
    dim3 grid((V_VERTS + 255) / 256, T_FRAMES, 1);
    se3_extract_kernel<<<grid, block>>>(canon, deform, neigh, nmask, out);
}

// round 3
// speedup vs baseline: 18.4726x; 18.4726x over previous
#include <cuda_runtime.h>
#include <math.h>

#define T_FRAMES 128
#define V_VERTS  5023
#define K_NBR    16

__device__ __forceinline__ void jacobi_rotate(float S[3][3], float Vm[3][3], int p, int q) {
    float Spq = S[p][q];
    if (fabsf(Spq) < 1e-20f) return;
    float tau = __fdividef(S[q][q] - S[p][p], 2.0f * Spq);
    float at = fabsf(tau);
    float t = __fdividef(1.0f, at + sqrtf(1.0f + at * at));
    if (tau < 0.0f) t = -t;
    float c = rsqrtf(1.0f + t * t);
    float s = t * c;

    float Spp = S[p][p], Sqq = S[q][q];
    S[p][p] = Spp - t * Spq;
    S[q][q] = Sqq + t * Spq;
    S[p][q] = 0.0f;
    S[q][p] = 0.0f;
    int r = 3 - p - q;
    float Srp = S[r][p], Srq = S[r][q];
    S[r][p] = c * Srp - s * Srq;  S[p][r] = S[r][p];
    S[r][q] = s * Srp + c * Srq;  S[q][r] = S[r][q];

    #pragma unroll
    for (int i = 0; i < 3; i++) {
        float vip = Vm[i][p], viq = Vm[i][q];
        Vm[i][p] = c * vip - s * viq;
        Vm[i][q] = s * vip + c * viq;
    }
}

__global__ void __launch_bounds__(256)
se3_extract_kernel(const float* __restrict__ canon,
                   const float* __restrict__ deform,
                   const int4* __restrict__ neighbors4,
                   const int4* __restrict__ nmask4,
                   float* __restrict__ out)
{
    int v = blockIdx.x * blockDim.x + threadIdx.x;
    int t = blockIdx.y;
    if (v >= V_VERTS) return;

    const float* ct = canon  + (size_t)t * V_VERTS * 3;
    const float* dt = deform + (size_t)t * V_VERTS * 3;

    float c0x = ct[v * 3 + 0], c0y = ct[v * 3 + 1], c0z = ct[v * 3 + 2];
    float d0x = dt[v * 3 + 0], d0y = dt[v * 3 + 1], d0z = dt[v * 3 + 2];

    // vectorized neighbor-index / mask loads: 16 ints = 4 x int4 each
    int   nidx[K_NBR];
    float nm[K_NBR];
    #pragma unroll
    for (int g = 0; g < 4; g++) {
        int4 ni = __ldg(&neighbors4[v * 4 + g]);
        int4 mi = __ldg(&nmask4[v * 4 + g]);
        nidx[g*4+0] = ni.x; nidx[g*4+1] = ni.y; nidx[g*4+2] = ni.z; nidx[g*4+3] = ni.w;
        nm[g*4+0] = mi.x ? 1.0f : 0.0f;
        nm[g*4+1] = mi.y ? 1.0f : 0.0f;
        nm[g*4+2] = mi.z ? 1.0f : 0.0f;
        nm[g*4+3] = mi.w ? 1.0f : 0.0f;
    }

    float a00 = 0.f, a01 = 0.f, a02 = 0.f;
    float a10 = 0.f, a11 = 0.f, a12 = 0.f;
    float a20 = 0.f, a21 = 0.f, a22 = 0.f;

    #pragma unroll
    for (int k = 0; k < K_NBR; k++) {
        int n = nidx[k];
        float m = nm[k];
        float px = __ldg(&ct[n * 3 + 0]) * m - c0x;
        float py = __ldg(&ct[n * 3 + 1]) * m - c0y;
        float pz = __ldg(&ct[n * 3 + 2]) * m - c0z;
        float qx = __ldg(&dt[n * 3 + 0]) * m - d0x;
        float qy = __ldg(&dt[n * 3 + 1]) * m - d0y;
        float qz = __ldg(&dt[n * 3 + 2]) * m - d0z;
        a00 += px * qx; a01 += px * qy; a02 += px * qz;
        a10 += py * qx; a11 += py * qy; a12 += py * qz;
        a20 += pz * qx; a21 += pz * qy; a22 += pz * qz;
    }

    float A[3][3] = {{a00, a01, a02}, {a10, a11, a12}, {a20, a21, a22}};

    // S = A^T A (symmetric)
    float S[3][3];
    #pragma unroll
    for (int i = 0; i < 3; i++)
        #pragma unroll
        for (int j = 0; j < 3; j++) {
            float acc = 0.0f;
            #pragma unroll
            for (int k = 0; k < 3; k++) acc += A[k][i] * A[k][j];
            S[i][j] = acc;
        }

    float Vm[3][3] = {{1, 0, 0}, {0, 1, 0}, {0, 0, 1}};
    #pragma unroll
    for (int sweep = 0; sweep < 6; sweep++) {
        jacobi_rotate(S, Vm, 0, 1);
        jacobi_rotate(S, Vm, 0, 2);
        jacobi_rotate(S, Vm, 1, 2);
    }

    // sort eigenvalues descending, track columns
    float w[3] = {S[0][0], S[1][1], S[2][2]};
    int idx[3] = {0, 1, 2};
    #pragma unroll
    for (int i = 0; i < 2; i++)
        #pragma unroll
        for (int j = 0; j < 2 - i; j++)
            if (w[idx[j]] < w[idx[j + 1]]) { int tmp = idx[j]; idx[j] = idx[j + 1]; idx[j + 1] = tmp; }

    float V0[3], V1[3], V2[3];
    #pragma unroll
    for (int i = 0; i < 3; i++) {
        V0[i] = Vm[i][idx[0]];
        V1[i] = Vm[i][idx[1]];
        V2[i] = Vm[i][idx[2]];
    }

    // U columns (unnormalized): u_i = A v_i
    float U0[3], U1[3], U2[3];
    #pragma unroll
    for (int i = 0; i < 3; i++) {
        U0[i] = A[i][0] * V0[0] + A[i][1] * V0[1] + A[i][2] * V0[2];
        U1[i] = A[i][0] * V1[0] + A[i][1] * V1[1] + A[i][2] * V1[2];
        U2[i] = A[i][0] * V2[0] + A[i][1] * V2[1] + A[i][2] * V2[2];
    }
    float n0 = U0[0]*U0[0] + U0[1]*U0[1] + U0[2]*U0[2];
    float n1 = U1[0]*U1[0] + U1[1]*U1[1] + U1[2]*U1[2];
    float n2 = U2[0]*U2[0] + U2[1]*U2[1] + U2[2]*U2[2];

    float R[3][3];
    if (n0 < 1e-30f) {
        R[0][0] = 1; R[0][1] = 0; R[0][2] = 0;
        R[1][0] = 0; R[1][1] = 1; R[1][2] = 0;
        R[2][0] = 0; R[2][1] = 0; R[2][2] = 1;
    } else {
        float inv0 = rsqrtf(n0);
        #pragma unroll
        for (int i = 0; i < 3; i++) U0[i] *= inv0;
        if (n1 > 1e-12f * n0) {
            float inv1 = rsqrtf(n1);
            #pragma unroll
            for (int i = 0; i < 3; i++) U1[i] *= inv1;
        } else {
            float ax = fabsf(U0[0]), ay = fabsf(U0[1]), az = fabsf(U0[2]);
            float e[3] = {0, 0, 0};
            if (ax <= ay && ax <= az) e[0] = 1; else if (ay <= az) e[1] = 1; else e[2] = 1;
            float d = e[0]*U0[0] + e[1]*U0[1] + e[2]*U0[2];
            float tx = e[0] - d*U0[0], ty = e[1] - d*U0[1], tz = e[2] - d*U0[2];
            float inr = rsqrtf(tx*tx + ty*ty + tz*tz);
            U1[0] = tx * inr; U1[1] = ty * inr; U1[2] = tz * inr;
        }
        if (n2 > 1e-12f * n0) {
            float inv2 = rsqrtf(n2);
            #pragma unroll
            for (int i = 0; i < 3; i++) U2[i] *= inv2;
        } else {
            U2[0] = U0[1]*U1[2] - U0[2]*U1[1];
            U2[1] = U0[2]*U1[0] - U0[0]*U1[2];
            U2[2] = U0[0]*U1[1] - U0[1]*U1[0];
        }

        float detU = U0[0]*(U1[1]*U2[2] - U1[2]*U2[1])
                   - U0[1]*(U1[0]*U2[2] - U1[2]*U2[0])
                   + U0[2]*(U1[0]*U2[1] - U1[1]*U2[0]);
        float detV = V0[0]*(V1[1]*V2[2] - V1[2]*V2[1])
                   - V0[1]*(V1[0]*V2[2] - V1[2]*V2[0])
                   + V0[2]*(V1[0]*V2[1] - V1[1]*V2[0]);
        float detUV = detU * detV;
        float d3 = (fabsf(detUV - 1.0f) > 1e-6f) ? detUV : 1.0f;

        #pragma unroll
        for (int a = 0; a < 3; a++)
            #pragma unroll
            for (int b = 0; b < 3; b++)
                R[a][b] = V0[a]*U0[b] + V1[a]*U1[b] + d3 * V2[a]*U2[b];
    }

    // ---- matrix -> quaternion (4-candidate selection) ----
    float m00 = R[0][0], m01 = R[0][1], m02 = R[0][2];
    float m10 = R[1][0], m11 = R[1][1], m12 = R[1][2];
    float m20 = R[2][0], m21 = R[2][1], m22 = R[2][2];

    float qa0 = 1.0f + m00 + m11 + m22;
    float qa1 = 1.0f + m00 - m11 - m22;
    float qa2 = 1.0f - m00 + m11 - m22;
    float qa3 = 1.0f - m00 - m11 + m22;
    qa0 = sqrtf(fmaxf(qa0, 0.0f));
    qa1 = sqrtf(fmaxf(qa1, 0.0f));
    qa2 = sqrtf(fmaxf(qa2, 0.0f));
    qa3 = sqrtf(fmaxf(qa3, 0.0f));

    float qabs[4] = {qa0, qa1, qa2, qa3};
    int imax = 0;
    #pragma unroll
    for (int i = 1; i < 4; i++) if (qabs[i] > qabs[imax]) imax = i;

    float cand[4];
    if (imax == 0) {
        cand[0] = qa0 * qa0; cand[1] = m21 - m12; cand[2] = m02 - m20; cand[3] = m10 - m01;
    } else if (imax == 1) {
        cand[0] = m21 - m12; cand[1] = qa1 * qa1; cand[2] = m01 + m10; cand[3] = m02 + m20;
    } else if (imax == 2) {
        cand[0] = m02 - m20; cand[1] = m10 + m01; cand[2] = qa2 * qa2; cand[3] = m12 + m21;
    } else {
        cand[0] = m10 - m01; cand[1] = m20 + m02; cand[2] = m21 + m12; cand[3] = qa3 * qa3;
    }
    float invd = __fdividef(1.0f, 2.0f * fmaxf(qabs[imax], 0.1f));

    size_t tv = (size_t)t * V_VERTS + v;
    float4* rot_out = (float4*)out;                          // [T*V] float4
    float*  trn_out = out + (size_t)T_FRAMES * V_VERTS * 4;  // [T*V, 3]

    rot_out[tv] = make_float4(cand[0] * invd, cand[1] * invd, cand[2] * invd, cand[3] * invd);

    trn_out[tv * 3 + 0] = d0x - c0x;
    trn_out[tv * 3 + 1] = d0y - c0y;
    trn_out[tv * 3 + 2] = d0z - c0z;
}

extern "C" void kernel_launch(void* const* d_in, const int* in_sizes, int n_in,
                              void* d_out, int out_size) {
    const float* canon  = (const float*)d_in[0];
    const float* deform = (const float*)d_in[1];
    const int4*  neigh  = (const int4*)d_in[2];
    const int4*  nmask  = (const int4*)d_in[3];
    float* out = (float*)d_out;

    dim3 block(256, 1, 1);
    dim3 grid((V_VERTS + 255) / 256, T_FRAMES, 1);
    se3_extract_kernel<<<grid, block>>>(canon, deform, neigh, nmask, out);
}

// round 4
// speedup vs baseline: 23.3981x; 1.2666x over previous
#include <cuda_runtime.h>
#include <math.h>

#define T_FRAMES 128
#define V_VERTS  5023
#define K_NBR    16
#define TV_TOTAL (T_FRAMES * V_VERTS)

// Repacked vertex storage: (x, y, z, 0) per vertex-time, 16B aligned.
__device__ float4 g_canon4[TV_TOTAL];
__device__ float4 g_deform4[TV_TOTAL];

// ---------------------------------------------------------------------------
// Kernel 1: repack xyz (stride 12B) -> float4 (stride 16B) and emit translation
// ---------------------------------------------------------------------------
__global__ void __launch_bounds__(256)
repack_kernel(const float* __restrict__ canon,
              const float* __restrict__ deform,
              float* __restrict__ trn_out)
{
    int i = blockIdx.x * blockDim.x + threadIdx.x;
    if (i >= TV_TOTAL) return;
    float cx = canon[i * 3 + 0], cy = canon[i * 3 + 1], cz = canon[i * 3 + 2];
    float dx = deform[i * 3 + 0], dy = deform[i * 3 + 1], dz = deform[i * 3 + 2];
    g_canon4[i]  = make_float4(cx, cy, cz, 0.0f);
    g_deform4[i] = make_float4(dx, dy, dz, 0.0f);
    trn_out[i * 3 + 0] = dx - cx;
    trn_out[i * 3 + 1] = dy - cy;
    trn_out[i * 3 + 2] = dz - cz;
}

// ---------------------------------------------------------------------------
// Kernel 2: SE(3) extraction
// ---------------------------------------------------------------------------
__device__ __forceinline__ void jacobi_rotate(float S[3][3], float Vm[3][3], int p, int q) {
    float Spq = S[p][q];
    if (fabsf(Spq) < 1e-20f) return;
    float tau = __fdividef(S[q][q] - S[p][p], 2.0f * Spq);
    float at = fabsf(tau);
    float t = __fdividef(1.0f, at + sqrtf(1.0f + at * at));
    if (tau < 0.0f) t = -t;
    float c = rsqrtf(1.0f + t * t);
    float s = t * c;

    float Spp = S[p][p], Sqq = S[q][q];
    S[p][p] = Spp - t * Spq;
    S[q][q] = Sqq + t * Spq;
    S[p][q] = 0.0f;
    S[q][p] = 0.0f;
    int r = 3 - p - q;
    float Srp = S[r][p], Srq = S[r][q];
    S[r][p] = c * Srp - s * Srq;  S[p][r] = S[r][p];
    S[r][q] = s * Srp + c * Srq;  S[q][r] = S[r][q];

    #pragma unroll
    for (int i = 0; i < 3; i++) {
        float vip = Vm[i][p], viq = Vm[i][q];
        Vm[i][p] = c * vip - s * viq;
        Vm[i][q] = s * vip + c * viq;
    }
}

__global__ void __launch_bounds__(128)
se3_extract_kernel(const int4* __restrict__ neighbors4,
                   const int4* __restrict__ nmask4,
                   float* __restrict__ rot_out)
{
    int v = blockIdx.x * blockDim.x + threadIdx.x;
    int t = blockIdx.y;
    if (v >= V_VERTS) return;

    const float4* ct4 = g_canon4  + (size_t)t * V_VERTS;
    const float4* dt4 = g_deform4 + (size_t)t * V_VERTS;

    float4 c0 = ct4[v];
    float4 d0 = dt4[v];

    int   nidx[K_NBR];
    float nm[K_NBR];
    #pragma unroll
    for (int g = 0; g < 4; g++) {
        int4 ni = __ldg(&neighbors4[v * 4 + g]);
        int4 mi = __ldg(&nmask4[v * 4 + g]);
        nidx[g*4+0] = ni.x; nidx[g*4+1] = ni.y; nidx[g*4+2] = ni.z; nidx[g*4+3] = ni.w;
        nm[g*4+0] = mi.x ? 1.0f : 0.0f;
        nm[g*4+1] = mi.y ? 1.0f : 0.0f;
        nm[g*4+2] = mi.z ? 1.0f : 0.0f;
        nm[g*4+3] = mi.w ? 1.0f : 0.0f;
    }

    float a00 = 0.f, a01 = 0.f, a02 = 0.f;
    float a10 = 0.f, a11 = 0.f, a12 = 0.f;
    float a20 = 0.f, a21 = 0.f, a22 = 0.f;

    #pragma unroll
    for (int k = 0; k < K_NBR; k++) {
        int n = nidx[k];
        float m = nm[k];
        float4 cn = __ldg(&ct4[n]);
        float4 dn = __ldg(&dt4[n]);
        float px = cn.x * m - c0.x;
        float py = cn.y * m - c0.y;
        float pz = cn.z * m - c0.z;
        float qx = dn.x * m - d0.x;
        float qy = dn.y * m - d0.y;
        float qz = dn.z * m - d0.z;
        a00 += px * qx; a01 += px * qy; a02 += px * qz;
        a10 += py * qx; a11 += py * qy; a12 += py * qz;
        a20 += pz * qx; a21 += pz * qy; a22 += pz * qz;
    }

    float A[3][3] = {{a00, a01, a02}, {a10, a11, a12}, {a20, a21, a22}};

    // S = A^T A
    float S[3][3];
    #pragma unroll
    for (int i = 0; i < 3; i++)
        #pragma unroll
        for (int j = 0; j < 3; j++) {
            float acc = 0.0f;
            #pragma unroll
            for (int k = 0; k < 3; k++) acc += A[k][i] * A[k][j];
            S[i][j] = acc;
        }

    float Vm[3][3] = {{1, 0, 0}, {0, 1, 0}, {0, 0, 1}};
    #pragma unroll
    for (int sweep = 0; sweep < 5; sweep++) {
        jacobi_rotate(S, Vm, 0, 1);
        jacobi_rotate(S, Vm, 0, 2);
        jacobi_rotate(S, Vm, 1, 2);
    }

    float w[3] = {S[0][0], S[1][1], S[2][2]};
    int idx[3] = {0, 1, 2};
    #pragma unroll
    for (int i = 0; i < 2; i++)
        #pragma unroll
        for (int j = 0; j < 2 - i; j++)
            if (w[idx[j]] < w[idx[j + 1]]) { int tmp = idx[j]; idx[j] = idx[j + 1]; idx[j + 1] = tmp; }

    float V0[3], V1[3], V2[3];
    #pragma unroll
    for (int i = 0; i < 3; i++) {
        V0[i] = Vm[i][idx[0]];
        V1[i] = Vm[i][idx[1]];
        V2[i] = Vm[i][idx[2]];
    }

    float U0[3], U1[3], U2[3];
    #pragma unroll
    for (int i = 0; i < 3; i++) {
        U0[i] = A[i][0] * V0[0] + A[i][1] * V0[1] + A[i][2] * V0[2];
        U1[i] = A[i][0] * V1[0] + A[i][1] * V1[1] + A[i][2] * V1[2];
        U2[i] = A[i][0] * V2[0] + A[i][1] * V2[1] + A[i][2] * V2[2];
    }
    float n0 = U0[0]*U0[0] + U0[1]*U0[1] + U0[2]*U0[2];
    float n1 = U1[0]*U1[0] + U1[1]*U1[1] + U1[2]*U1[2];
    float n2 = U2[0]*U2[0] + U2[1]*U2[1] + U2[2]*U2[2];

    float R[3][3];
    if (n0 < 1e-30f) {
        R[0][0] = 1; R[0][1] = 0; R[0][2] = 0;
        R[1][0] = 0; R[1][1] = 1; R[1][2] = 0;
        R[2][0] = 0; R[2][1] = 0; R[2][2] = 1;
    } else {
        float inv0 = rsqrtf(n0);
        #pragma unroll
        for (int i = 0; i < 3; i++) U0[i] *= inv0;
        if (n1 > 1e-12f * n0) {
            float inv1 = rsqrtf(n1);
            #pragma unroll
            for (int i = 0; i < 3; i++) U1[i] *= inv1;
        } else {
            float ax = fabsf(U0[0]), ay = fabsf(U0[1]), az = fabsf(U0[2]);
            float e[3] = {0, 0, 0};
            if (ax <= ay && ax <= az) e[0] = 1; else if (ay <= az) e[1] = 1; else e[2] = 1;
            float d = e[0]*U0[0] + e[1]*U0[1] + e[2]*U0[2];
            float tx = e[0] - d*U0[0], ty = e[1] - d*U0[1], tz = e[2] - d*U0[2];
            float inr = rsqrtf(tx*tx + ty*ty + tz*tz);
            U1[0] = tx * inr; U1[1] = ty * inr; U1[2] = tz * inr;
        }
        if (n2 > 1e-12f * n0) {
            float inv2 = rsqrtf(n2);
            #pragma unroll
            for (int i = 0; i < 3; i++) U2[i] *= inv2;
        } else {
            U2[0] = U0[1]*U1[2] - U0[2]*U1[1];
            U2[1] = U0[2]*U1[0] - U0[0]*U1[2];
            U2[2] = U0[0]*U1[1] - U0[1]*U1[0];
        }

        float detU = U0[0]*(U1[1]*U2[2] - U1[2]*U2[1])
                   - U0[1]*(U1[0]*U2[2] - U1[2]*U2[0])
                   + U0[2]*(U1[0]*U2[1] - U1[1]*U2[0]);
        float detV = V0[0]*(V1[1]*V2[2] - V1[2]*V2[1])
                   - V0[1]*(V1[0]*V2[2] - V1[2]*V2[0])
                   + V0[2]*(V1[0]*V2[1] - V1[1]*V2[0]);
        float detUV = detU * detV;
        float d3 = (fabsf(detUV - 1.0f) > 1e-6f) ? detUV : 1.0f;

        #pragma unroll
        for (int a = 0; a < 3; a++)
            #pragma unroll
            for (int b = 0; b < 3; b++)
                R[a][b] = V0[a]*U0[b] + V1[a]*U1[b] + d3 * V2[a]*U2[b];
    }

    float m00 = R[0][0], m01 = R[0][1], m02 = R[0][2];
    float m10 = R[1][0], m11 = R[1][1], m12 = R[1][2];
    float m20 = R[2][0], m21 = R[2][1], m22 = R[2][2];

    float qa0 = sqrtf(fmaxf(1.0f + m00 + m11 + m22, 0.0f));
    float qa1 = sqrtf(fmaxf(1.0f + m00 - m11 - m22, 0.0f));
    float qa2 = sqrtf(fmaxf(1.0f - m00 + m11 - m22, 0.0f));
    float qa3 = sqrtf(fmaxf(1.0f - m00 - m11 + m22, 0.0f));

    float qabs[4] = {qa0, qa1, qa2, qa3};
    int imax = 0;
    #pragma unroll
    for (int i = 1; i < 4; i++) if (qabs[i] > qabs[imax]) imax = i;

    float cand[4];
    if (imax == 0) {
        cand[0] = qa0 * qa0; cand[1] = m21 - m12; cand[2] = m02 - m20; cand[3] = m10 - m01;
    } else if (imax == 1) {
        cand[0] = m21 - m12; cand[1] = qa1 * qa1; cand[2] = m01 + m10; cand[3] = m02 + m20;
    } else if (imax == 2) {
        cand[0] = m02 - m20; cand[1] = m10 + m01; cand[2] = qa2 * qa2; cand[3] = m12 + m21;
    } else {
        cand[0] = m10 - m01; cand[1] = m20 + m02; cand[2] = m21 + m12; cand[3] = qa3 * qa3;
    }
    float invd = __fdividef(1.0f, 2.0f * fmaxf(qabs[imax], 0.1f));

    size_t tv = (size_t)t * V_VERTS + v;
    ((float4*)rot_out)[tv] = make_float4(cand[0] * invd, cand[1] * invd,
                                         cand[2] * invd, cand[3] * invd);
}

extern "C" void kernel_launch(void* const* d_in, const int* in_sizes, int n_in,
                              void* d_out, int out_size) {
    const float* canon  = (const float*)d_in[0];
    const float* deform = (const float*)d_in[1];
    const int4*  neigh  = (const int4*)d_in[2];
    const int4*  nmask  = (const int4*)d_in[3];
    float* out = (float*)d_out;
    float* rot_out = out;                                   // [T*V, 4]
    float* trn_out = out + (size_t)T_FRAMES * V_VERTS * 4;  // [T*V, 3]

    repack_kernel<<<(TV_TOTAL + 255) / 256, 256>>>(canon, deform, trn_out);

    dim3 block(128, 1, 1);
    dim3 grid((V_VERTS + 127) / 128, T_FRAMES, 1);
    se3_extract_kernel<<<grid, block>>>(neigh, nmask, rot_out);
}

// round 5
// speedup vs baseline: 33.9196x; 1.4497x over previous
#include <cuda_runtime.h>
#include <math.h>

#define T_FRAMES 128
#define V_VERTS  5023
#define V_PAD    5024
#define K_NBR    16
#define TV_TOTAL (T_FRAMES * V_VERTS)
#define BLOCK    512

#define SMEM_BYTES (2 * V_PAD * 16)

__device__ __forceinline__ void jacobi_rotate(float S[3][3], float Vm[3][3], int p, int q) {
    float Spq = S[p][q];
    if (fabsf(Spq) < 1e-20f) return;
    float tau = __fdividef(S[q][q] - S[p][p], 2.0f * Spq);
    float at = fabsf(tau);
    float t = __fdividef(1.0f, at + sqrtf(1.0f + at * at));
    if (tau < 0.0f) t = -t;
    float c = rsqrtf(1.0f + t * t);
    float s = t * c;

    float Spp = S[p][p], Sqq = S[q][q];
    S[p][p] = Spp - t * Spq;
    S[q][q] = Sqq + t * Spq;
    S[p][q] = 0.0f;
    S[q][p] = 0.0f;
    int r = 3 - p - q;
    float Srp = S[r][p], Srq = S[r][q];
    S[r][p] = c * Srp - s * Srq;  S[p][r] = S[r][p];
    S[r][q] = s * Srp + c * Srq;  S[q][r] = S[r][q];

    #pragma unroll
    for (int i = 0; i < 3; i++) {
        float vip = Vm[i][p], viq = Vm[i][q];
        Vm[i][p] = c * vip - s * viq;
        Vm[i][q] = s * vip + c * viq;
    }
}

__global__ void __launch_bounds__(BLOCK, 1)
se3_extract_kernel(const float* __restrict__ canon,
                   const float* __restrict__ deform,
                   const int4* __restrict__ neighbors4,
                   const int4* __restrict__ nmask4,
                   float* __restrict__ rot_out,
                   float* __restrict__ trn_out)
{
    extern __shared__ float4 smem[];
    float4* sc = smem;           // canonical, V_PAD entries
    float4* sd = smem + V_PAD;   // deformed

    int t   = blockIdx.x;
    int tid = threadIdx.x;

    const float* ct = canon  + (size_t)t * V_VERTS * 3;
    const float* dt = deform + (size_t)t * V_VERTS * 3;

    // stage frame into smem: xyz (12B stride) -> float4 (16B stride)
    float* scf = (float*)sc;
    float* sdf = (float*)sd;
    for (int i = tid; i < V_VERTS * 3; i += BLOCK) {
        int v = i / 3, c = i - v * 3;
        scf[v * 4 + c] = ct[i];
        sdf[v * 4 + c] = dt[i];
    }
    __syncthreads();

    for (int v = tid; v < V_VERTS; v += BLOCK) {
        float4 c0 = sc[v];
        float4 d0 = sd[v];

        int   nidx[K_NBR];
        float nm[K_NBR];
        #pragma unroll
        for (int g = 0; g < 4; g++) {
            int4 ni = __ldg(&neighbors4[v * 4 + g]);
            int4 mi = __ldg(&nmask4[v * 4 + g]);
            nidx[g*4+0] = ni.x; nidx[g*4+1] = ni.y; nidx[g*4+2] = ni.z; nidx[g*4+3] = ni.w;
            nm[g*4+0] = mi.x ? 1.0f : 0.0f;
            nm[g*4+1] = mi.y ? 1.0f : 0.0f;
            nm[g*4+2] = mi.z ? 1.0f : 0.0f;
            nm[g*4+3] = mi.w ? 1.0f : 0.0f;
        }

        float a00 = 0.f, a01 = 0.f, a02 = 0.f;
        float a10 = 0.f, a11 = 0.f, a12 = 0.f;
        float a20 = 0.f, a21 = 0.f, a22 = 0.f;

        #pragma unroll
        for (int k = 0; k < K_NBR; k++) {
            int n = nidx[k];
            float m = nm[k];
            float4 cn = sc[n];
            float4 dn = sd[n];
            float px = cn.x * m - c0.x;
            float py = cn.y * m - c0.y;
            float pz = cn.z * m - c0.z;
            float qx = dn.x * m - d0.x;
            float qy = dn.y * m - d0.y;
            float qz = dn.z * m - d0.z;
            a00 += px * qx; a01 += px * qy; a02 += px * qz;
            a10 += py * qx; a11 += py * qy; a12 += py * qz;
            a20 += pz * qx; a21 += pz * qy; a22 += pz * qz;
        }

        float A[3][3] = {{a00, a01, a02}, {a10, a11, a12}, {a20, a21, a22}};

        // S = A^T A
        float S[3][3];
        #pragma unroll
        for (int i = 0; i < 3; i++)
            #pragma unroll
            for (int j = 0; j < 3; j++) {
                float acc = 0.0f;
                #pragma unroll
                for (int k = 0; k < 3; k++) acc += A[k][i] * A[k][j];
                S[i][j] = acc;
            }

        float Vm[3][3] = {{1, 0, 0}, {0, 1, 0}, {0, 0, 1}};
        #pragma unroll
        for (int sweep = 0; sweep < 5; sweep++) {
            jacobi_rotate(S, Vm, 0, 1);
            jacobi_rotate(S, Vm, 0, 2);
            jacobi_rotate(S, Vm, 1, 2);
        }

        // branchless descending sort of (eigenvalue, column) triples in registers
        float w0 = S[0][0], w1 = S[1][1], w2 = S[2][2];
        float c00 = Vm[0][0], c01 = Vm[1][0], c02 = Vm[2][0];
        float c10 = Vm[0][1], c11 = Vm[1][1], c12 = Vm[2][1];
        float c20 = Vm[0][2], c21 = Vm[1][2], c22 = Vm[2][2];
        {
            bool sw = w0 < w1;
            float tw = sw ? w1 : w0;  w1 = sw ? w0 : w1;  w0 = tw;
            float tx = sw ? c10 : c00, ty = sw ? c11 : c01, tz = sw ? c12 : c02;
            c10 = sw ? c00 : c10; c11 = sw ? c01 : c11; c12 = sw ? c02 : c12;
            c00 = tx; c01 = ty; c02 = tz;
        }
        {
            bool sw = w0 < w2;
            float tw = sw ? w2 : w0;  w2 = sw ? w0 : w2;  w0 = tw;
            float tx = sw ? c20 : c00, ty = sw ? c21 : c01, tz = sw ? c22 : c02;
            c20 = sw ? c00 : c20; c21 = sw ? c01 : c21; c22 = sw ? c02 : c22;
            c00 = tx; c01 = ty; c02 = tz;
        }
        {
            bool sw = w1 < w2;
            float tw = sw ? w2 : w1;  w2 = sw ? w1 : w2;  w1 = tw;
            float tx = sw ? c20 : c10, ty = sw ? c21 : c11, tz = sw ? c22 : c12;
            c20 = sw ? c10 : c20; c21 = sw ? c11 : c21; c22 = sw ? c12 : c22;
            c10 = tx; c11 = ty; c12 = tz;
        }
        float V0[3] = {c00, c01, c02};
        float V1[3] = {c10, c11, c12};
        float V2[3] = {c20, c21, c22};

        float U0[3], U1[3], U2[3];
        #pragma unroll
        for (int i = 0; i < 3; i++) {
            U0[i] = A[i][0] * V0[0] + A[i][1] * V0[1] + A[i][2] * V0[2];
            U1[i] = A[i][0] * V1[0] + A[i][1] * V1[1] + A[i][2] * V1[2];
            U2[i] = A[i][0] * V2[0] + A[i][1] * V2[1] + A[i][2] * V2[2];
        }
        float n0 = U0[0]*U0[0] + U0[1]*U0[1] + U0[2]*U0[2];
        float n1 = U1[0]*U1[0] + U1[1]*U1[1] + U1[2]*U1[2];
        float n2 = U2[0]*U2[0] + U2[1]*U2[1] + U2[2]*U2[2];

        float R[3][3];
        if (n0 < 1e-30f) {
            R[0][0] = 1; R[0][1] = 0; R[0][2] = 0;
            R[1][0] = 0; R[1][1] = 1; R[1][2] = 0;
            R[2][0] = 0; R[2][1] = 0; R[2][2] = 1;
        } else {
            float inv0 = rsqrtf(n0);
            #pragma unroll
            for (int i = 0; i < 3; i++) U0[i] *= inv0;
            if (n1 > 1e-12f * n0) {
                float inv1 = rsqrtf(n1);
                #pragma unroll
                for (int i = 0; i < 3; i++) U1[i] *= inv1;
            } else {
                float ax = fabsf(U0[0]), ay = fabsf(U0[1]), az = fabsf(U0[2]);
                float e[3] = {0, 0, 0};
                if (ax <= ay && ax <= az) e[0] = 1; else if (ay <= az) e[1] = 1; else e[2] = 1;
                float d = e[0]*U0[0] + e[1]*U0[1] + e[2]*U0[2];
                float tx = e[0] - d*U0[0], ty = e[1] - d*U0[1], tz = e[2] - d*U0[2];
                float inr = rsqrtf(tx*tx + ty*ty + tz*tz);
                U1[0] = tx * inr; U1[1] = ty * inr; U1[2] = tz * inr;
            }
            if (n2 > 1e-12f * n0) {
                float inv2 = rsqrtf(n2);
                #pragma unroll
                for (int i = 0; i < 3; i++) U2[i] *= inv2;
            } else {
                U2[0] = U0[1]*U1[2] - U0[2]*U1[1];
                U2[1] = U0[2]*U1[0] - U0[0]*U1[2];
                U2[2] = U0[0]*U1[1] - U0[1]*U1[0];
            }

            float detU = U0[0]*(U1[1]*U2[2] - U1[2]*U2[1])
                       - U0[1]*(U1[0]*U2[2] - U1[2]*U2[0])
                       + U0[2]*(U1[0]*U2[1] - U1[1]*U2[0]);
            float detV = V0[0]*(V1[1]*V2[2] - V1[2]*V2[1])
                       - V0[1]*(V1[0]*V2[2] - V1[2]*V2[0])
                       + V0[2]*(V1[0]*V2[1] - V1[1]*V2[0]);
            float detUV = detU * detV;
            float d3 = (fabsf(detUV - 1.0f) > 1e-6f) ? detUV : 1.0f;

            #pragma unroll
            for (int a = 0; a < 3; a++)
                #pragma unroll
                for (int b = 0; b < 3; b++)
                    R[a][b] = V0[a]*U0[b] + V1[a]*U1[b] + d3 * V2[a]*U2[b];
        }

        float m00 = R[0][0], m01 = R[0][1], m02 = R[0][2];
        float m10 = R[1][0], m11 = R[1][1], m12 = R[1][2];
        float m20 = R[2][0], m21 = R[2][1], m22 = R[2][2];

        float qa0 = sqrtf(fmaxf(1.0f + m00 + m11 + m22, 0.0f));
        float qa1 = sqrtf(fmaxf(1.0f + m00 - m11 - m22, 0.0f));
        float qa2 = sqrtf(fmaxf(1.0f - m00 + m11 - m22, 0.0f));
        float qa3 = sqrtf(fmaxf(1.0f - m00 - m11 + m22, 0.0f));

        float qabs[4] = {qa0, qa1, qa2, qa3};
        int imax = 0;
        #pragma unroll
        for (int i = 1; i < 4; i++) if (qabs[i] > qabs[imax]) imax = i;

        float cand[4];
        if (imax == 0) {
            cand[0] = qa0 * qa0; cand[1] = m21 - m12; cand[2] = m02 - m20; cand[3] = m10 - m01;
        } else if (imax == 1) {
            cand[0] = m21 - m12; cand[1] = qa1 * qa1; cand[2] = m01 + m10; cand[3] = m02 + m20;
        } else if (imax == 2) {
            cand[0] = m02 - m20; cand[1] = m10 + m01; cand[2] = qa2 * qa2; cand[3] = m12 + m21;
        } else {
            cand[0] = m10 - m01; cand[1] = m20 + m02; cand[2] = m21 + m12; cand[3] = qa3 * qa3;
        }
        float invd = __fdividef(1.0f, 2.0f * fmaxf(qabs[imax], 0.1f));

        size_t tv = (size_t)t * V_VERTS + v;
        ((float4*)rot_out)[tv] = make_float4(cand[0] * invd, cand[1] * invd,
                                             cand[2] * invd, cand[3] * invd);
        trn_out[tv * 3 + 0] = d0.x - c0.x;
        trn_out[tv * 3 + 1] = d0.y - c0.y;
        trn_out[tv * 3 + 2] = d0.z - c0.z;
    }
}

extern "C" void kernel_launch(void* const* d_in, const int* in_sizes, int n_in,
                              void* d_out, int out_size) {
    const float* canon  = (const float*)d_in[0];
    const float* deform = (const float*)d_in[1];
    const int4*  neigh  = (const int4*)d_in[2];
    const int4*  nmask  = (const int4*)d_in[3];
    float* out = (float*)d_out;
    float* rot_out = out;                                   // [T*V, 4]
    float* trn_out = out + (size_t)T_FRAMES * V_VERTS * 4;  // [T*V, 3]

    static bool attr_set = false;
    if (!attr_set) {
        cudaFuncSetAttribute(se3_extract_kernel,
                             cudaFuncAttributeMaxDynamicSharedMemorySize, SMEM_BYTES);
        attr_set = true;
    }

    se3_extract_kernel<<<T_FRAMES, BLOCK, SMEM_BYTES>>>(canon, deform, neigh, nmask,
                                                        rot_out, trn_out);
}

// round 7
// speedup vs baseline: 36.5305x; 1.0770x over previous
#include <cuda_runtime.h>
#include <math.h>

#define T_FRAMES 128
#define V_VERTS  5023
#define V_PAD    5024
#define K_NBR    16
#define BLOCK    768

#define SMEM_BYTES (2 * V_PAD * 16)

__device__ __forceinline__ void jacobi_rotate(float S[3][3], float Vm[3][3], int p, int q) {
    float Spq = S[p][q];
    float tau = __fdividef(S[q][q] - S[p][p], 2.0f * Spq);
    float at = fabsf(tau);
    float t = __fdividef(1.0f, at + sqrtf(1.0f + at * at));
    t = (tau < 0.0f) ? -t : t;
    t = (fabsf(Spq) < 1e-25f) ? 0.0f : t;   // branchless guard (select)
    float c = rsqrtf(1.0f + t * t);
    float s = t * c;

    float Spp = S[p][p], Sqq = S[q][q];
    S[p][p] = Spp - t * Spq;
    S[q][q] = Sqq + t * Spq;
    S[p][q] = 0.0f;
    S[q][p] = 0.0f;
    int r = 3 - p - q;
    float Srp = S[r][p], Srq = S[r][q];
    S[r][p] = c * Srp - s * Srq;  S[p][r] = S[r][p];
    S[r][q] = s * Srp + c * Srq;  S[q][r] = S[r][q];

    #pragma unroll
    for (int i = 0; i < 3; i++) {
        float vip = Vm[i][p], viq = Vm[i][q];
        Vm[i][p] = c * vip - s * viq;
        Vm[i][q] = s * vip + c * viq;
    }
}

__global__ void __launch_bounds__(BLOCK, 1)
se3_extract_kernel(const float* __restrict__ canon,
                   const float* __restrict__ deform,
                   const int4* __restrict__ neighbors4,
                   const int4* __restrict__ nmask4,
                   float* __restrict__ rot_out,
                   float* __restrict__ trn_out)
{
    extern __shared__ float4 smem[];
    float4* sc = smem;           // canonical, V_PAD entries
    float4* sd = smem + V_PAD;   // deformed

    int t   = blockIdx.x;
    int tid = threadIdx.x;

    const float* ct = canon  + (size_t)t * V_VERTS * 3;
    const float* dt = deform + (size_t)t * V_VERTS * 3;

    // stage frame into smem: xyz (12B stride) -> float4 (16B stride)
    float* scf = (float*)sc;
    float* sdf = (float*)sd;
    for (int i = tid; i < V_VERTS * 3; i += BLOCK) {
        int v = i / 3, c = i - v * 3;
        scf[v * 4 + c] = ct[i];
        sdf[v * 4 + c] = dt[i];
    }
    __syncthreads();

    for (int v = tid; v < V_VERTS; v += BLOCK) {
        float4 c0 = sc[v];
        float4 d0 = sd[v];

        int   nidx[K_NBR];
        float nm[K_NBR];
        #pragma unroll
        for (int g = 0; g < 4; g++) {
            int4 ni = __ldg(&neighbors4[v * 4 + g]);
            int4 mi = __ldg(&nmask4[v * 4 + g]);
            nidx[g*4+0] = ni.x; nidx[g*4+1] = ni.y; nidx[g*4+2] = ni.z; nidx[g*4+3] = ni.w;
            nm[g*4+0] = mi.x ? 1.0f : 0.0f;
            nm[g*4+1] = mi.y ? 1.0f : 0.0f;
            nm[g*4+2] = mi.z ? 1.0f : 0.0f;
            nm[g*4+3] = mi.w ? 1.0f : 0.0f;
        }

        float a00 = 0.f, a01 = 0.f, a02 = 0.f;
        float a10 = 0.f, a11 = 0.f, a12 = 0.f;
        float a20 = 0.f, a21 = 0.f, a22 = 0.f;

        #pragma unroll
        for (int k = 0; k < K_NBR; k++) {
            int n = nidx[k];
            float m = nm[k];
            float4 cn = sc[n];
            float4 dn = sd[n];
            float px = cn.x * m - c0.x;
            float py = cn.y * m - c0.y;
            float pz = cn.z * m - c0.z;
            float qx = dn.x * m - d0.x;
            float qy = dn.y * m - d0.y;
            float qz = dn.z * m - d0.z;
            a00 += px * qx; a01 += px * qy; a02 += px * qz;
            a10 += py * qx; a11 += py * qy; a12 += py * qz;
            a20 += pz * qx; a21 += pz * qy; a22 += pz * qz;
        }

        float A[3][3] = {{a00, a01, a02}, {a10, a11, a12}, {a20, a21, a22}};

        // S = A^T A
        float S[3][3];
        #pragma unroll
        for (int i = 0; i < 3; i++)
            #pragma unroll
            for (int j = 0; j < 3; j++) {
                float acc = 0.0f;
                #pragma unroll
                for (int k = 0; k < 3; k++) acc += A[k][i] * A[k][j];
                S[i][j] = acc;
            }

        float Vm[3][3] = {{1, 0, 0}, {0, 1, 0}, {0, 0, 1}};
        #pragma unroll
        for (int sweep = 0; sweep < 3; sweep++) {
            jacobi_rotate(S, Vm, 0, 1);
            jacobi_rotate(S, Vm, 0, 2);
            jacobi_rotate(S, Vm, 1, 2);
        }

        // branchless descending sort of (eigenvalue, column) triples in registers
        float w0 = S[0][0], w1 = S[1][1], w2 = S[2][2];
        float c00 = Vm[0][0], c01 = Vm[1][0], c02 = Vm[2][0];
        float c10 = Vm[0][1], c11 = Vm[1][1], c12 = Vm[2][1];
        float c20 = Vm[0][2], c21 = Vm[1][2], c22 = Vm[2][2];
        {
            bool sw = w0 < w1;
            float tw = sw ? w1 : w0;  w1 = sw ? w0 : w1;  w0 = tw;
            float tx = sw ? c10 : c00, ty = sw ? c11 : c01, tz = sw ? c12 : c02;
            c10 = sw ? c00 : c10; c11 = sw ? c01 : c11; c12 = sw ? c02 : c12;
            c00 = tx; c01 = ty; c02 = tz;
        }
        {
            bool sw = w0 < w2;
            float tw = sw ? w2 : w0;  w2 = sw ? w0 : w2;  w0 = tw;
            float tx = sw ? c20 : c00, ty = sw ? c21 : c01, tz = sw ? c22 : c02;
            c20 = sw ? c00 : c20; c21 = sw ? c01 : c21; c22 = sw ? c02 : c22;
            c00 = tx; c01 = ty; c02 = tz;
        }
        {
            bool sw = w1 < w2;
            float tw = sw ? w2 : w1;  w2 = sw ? w1 : w2;  w1 = tw;
            float tx = sw ? c20 : c10, ty = sw ? c21 : c11, tz = sw ? c22 : c12;
            c20 = sw ? c10 : c20; c21 = sw ? c11 : c21; c22 = sw ? c12 : c22;
            c10 = tx; c11 = ty; c12 = tz;
        }
        float V0[3] = {c00, c01, c02};
        float V1[3] = {c10, c11, c12};
        float V2[3] = {c20, c21, c22};

        float U0[3], U1[3], U2[3];
        #pragma unroll
        for (int i = 0; i < 3; i++) {
            U0[i] = A[i][0] * V0[0] + A[i][1] * V0[1] + A[i][2] * V0[2];
            U1[i] = A[i][0] * V1[0] + A[i][1] * V1[1] + A[i][2] * V1[2];
            U2[i] = A[i][0] * V2[0] + A[i][1] * V2[1] + A[i][2] * V2[2];
        }
        float n0 = U0[0]*U0[0] + U0[1]*U0[1] + U0[2]*U0[2];
        float n1 = U1[0]*U1[0] + U1[1]*U1[1] + U1[2]*U1[2];
        float n2 = U2[0]*U2[0] + U2[1]*U2[1] + U2[2]*U2[2];

        float R[3][3];
        if (n0 < 1e-30f) {
            R[0][0] = 1; R[0][1] = 0; R[0][2] = 0;
            R[1][0] = 0; R[1][1] = 1; R[1][2] = 0;
            R[2][0] = 0; R[2][1] = 0; R[2][2] = 1;
        } else {
            float inv0 = rsqrtf(n0);
            #pragma unroll
            for (int i = 0; i < 3; i++) U0[i] *= inv0;
            if (n1 > 1e-12f * n0) {
                float inv1 = rsqrtf(n1);
                #pragma unroll
                for (int i = 0; i < 3; i++) U1[i] *= inv1;
            } else {
                float ax = fabsf(U0[0]), ay = fabsf(U0[1]), az = fabsf(U0[2]);
                float e[3] = {0, 0, 0};
                if (ax <= ay && ax <= az) e[0] = 1; else if (ay <= az) e[1] = 1; else e[2] = 1;
                float d = e[0]*U0[0] + e[1]*U0[1] + e[2]*U0[2];
                float tx = e[0] - d*U0[0], ty = e[1] - d*U0[1], tz = e[2] - d*U0[2];
                float inr = rsqrtf(tx*tx + ty*ty + tz*tz);
                U1[0] = tx * inr; U1[1] = ty * inr; U1[2] = tz * inr;
            }
            if (n2 > 1e-12f * n0) {
                float inv2 = rsqrtf(n2);
                #pragma unroll
                for (int i = 0; i < 3; i++) U2[i] *= inv2;
            } else {
                U2[0] = U0[1]*U1[2] - U0[2]*U1[1];
                U2[1] = U0[2]*U1[0] - U0[0]*U1[2];
                U2[2] = U0[0]*U1[1] - U0[1]*U1[0];
            }

            float detU = U0[0]*(U1[1]*U2[2] - U1[2]*U2[1])
                       - U0[1]*(U1[0]*U2[2] - U1[2]*U2[0])
                       + U0[2]*(U1[0]*U2[1] - U1[1]*U2[0]);
            float detV = V0[0]*(V1[1]*V2[2] - V1[2]*V2[1])
                       - V0[1]*(V1[0]*V2[2] - V1[2]*V2[0])
                       + V0[2]*(V1[0]*V2[1] - V1[1]*V2[0]);
            float detUV = detU * detV;
            float d3 = (fabsf(detUV - 1.0f) > 1e-6f) ? detUV : 1.0f;

            #pragma unroll
            for (int a = 0; a < 3; a++)
                #pragma unroll
                for (int b = 0; b < 3; b++)
                    R[a][b] = V0[a]*U0[b] + V1[a]*U1[b] + d3 * V2[a]*U2[b];
        }

        float m00 = R[0][0], m01 = R[0][1], m02 = R[0][2];
        float m10 = R[1][0], m11 = R[1][1], m12 = R[1][2];
        float m20 = R[2][0], m21 = R[2][1], m22 = R[2][2];

        float qa0 = sqrtf(fmaxf(1.0f + m00 + m11 + m22, 0.0f));
        float qa1 = sqrtf(fmaxf(1.0f + m00 - m11 - m22, 0.0f));
        float qa2 = sqrtf(fmaxf(1.0f - m00 + m11 - m22, 0.0f));
        float qa3 = sqrtf(fmaxf(1.0f - m00 - m11 + m22, 0.0f));

        // branchless argmax (first max on ties)
        int imax = 0; float qmax = qa0;
        imax = (qa1 > qmax) ? 1 : imax;  qmax = (qa1 > qmax) ? qa1 : qmax;
        imax = (qa2 > qmax) ? 2 : imax;  qmax = (qa2 > qmax) ? qa2 : qmax;
        imax = (qa3 > qmax) ? 3 : imax;  qmax = (qa3 > qmax) ? qa3 : qmax;

        // branchless candidate-row selection
        bool b0 = (imax == 0), b1 = (imax == 1), b2 = (imax == 2);
        float cand0 = b0 ? qa0 * qa0 : (b1 ? m21 - m12 : (b2 ? m02 - m20 : m10 - m01));
        float cand1 = b0 ? m21 - m12 : (b1 ? qa1 * qa1 : (b2 ? m10 + m01 : m20 + m02));
        float cand2 = b0 ? m02 - m20 : (b1 ? m01 + m10 : (b2 ? qa2 * qa2 : m21 + m12));
        float cand3 = b0 ? m10 - m01 : (b1 ? m02 + m20 : (b2 ? m12 + m21 : qa3 * qa3));

        float invd = __fdividef(1.0f, 2.0f * fmaxf(qmax, 0.1f));

        size_t tv = (size_t)t * V_VERTS + v;
        ((float4*)rot_out)[tv] = make_float4(cand0 * invd, cand1 * invd,
                                             cand2 * invd, cand3 * invd);
        trn_out[tv * 3 + 0] = d0.x - c0.x;
        trn_out[tv * 3 + 1] = d0.y - c0.y;
        trn_out[tv * 3 + 2] = d0.z - c0.z;
    }
}

extern "C" void kernel_launch(void* const* d_in, const int* in_sizes, int n_in,
                              void* d_out, int out_size) {
    const float* canon  = (const float*)d_in[0];
    const float* deform = (const float*)d_in[1];
    const int4*  neigh  = (const int4*)d_in[2];
    const int4*  nmask  = (const int4*)d_in[3];
    float* out = (float*)d_out;
    float* rot_out = out;                                   // [T*V, 4]
    float* trn_out = out + (size_t)T_FRAMES * V_VERTS * 4;  // [T*V, 3]

    static bool attr_set = false;
    if (!attr_set) {
        cudaFuncSetAttribute(se3_extract_kernel,
                             cudaFuncAttributeMaxDynamicSharedMemorySize, SMEM_BYTES);
        attr_set = true;
    }

    se3_extract_kernel<<<T_FRAMES, BLOCK, SMEM_BYTES>>>(canon, deform, neigh, nmask,
                                                        rot_out, trn_out);
}